// round 3
// baseline (speedup 1.0000x reference)
#include <cuda_runtime.h>

// YoloV3Decoder: predictions (1, 145152, 85) fp32 -> tuple flattened as fp32:
//   [0 .. 4N)    bboxes (x,y,w,h)
//   [4N .. 5N)   scores
//   [5N .. 6N)   class_pred (as float)
//   [6N .. 12N)  detections (x,y,w,h,class_conf,class_pred)
// score_threshold input is unused by the reference outputs.

#define NUM_ANCHORS 145152
#define NUM_CH 85
#define NUM_CLASSES 80
#define ROWS_PER_BLOCK 128
#define THREADS 256

__global__ __launch_bounds__(THREADS) void yolo_decode_kernel(
    const float* __restrict__ pred, float* __restrict__ out)
{
    __shared__ float tile[ROWS_PER_BLOCK * NUM_CH];  // 43520 bytes

    const int tid = threadIdx.x;
    const int base_row = blockIdx.x * ROWS_PER_BLOCK;

    // ---- Phase 1: coalesced staging, 8 warps issuing float4 LDGs ----
    // 128 rows * 85 floats = 10880 floats = 2720 float4. Tile base is 16B aligned
    // (blockIdx * 43520 bytes).
    {
        const float4* __restrict__ src =
            reinterpret_cast<const float4*>(pred + (size_t)base_row * NUM_CH);
        float4* __restrict__ dst = reinterpret_cast<float4*>(tile);
        const int n4 = ROWS_PER_BLOCK * NUM_CH / 4;  // 2720
        #pragma unroll 4
        for (int i = tid; i < n4; i += THREADS) {
            dst[i] = src[i];
        }
    }
    __syncthreads();

    // ---- Phase 2: two threads per row; each scans 40 classes ----
    const int r    = tid >> 1;       // local row 0..127
    const int half = tid & 1;        // which 40-class chunk
    const int a    = base_row + r;   // global anchor
    const float* __restrict__ row = tile + r * NUM_CH;

    // Local argmax over classes [half*40, half*40+40)
    const int cbase = half * 40;
    float cmax = row[5 + cbase];
    int   cidx = cbase;
    #pragma unroll
    for (int c = 1; c < 40; ++c) {
        const float v = row[5 + cbase + c];
        if (v > cmax) { cmax = v; cidx = cbase + c; }
    }

    // Combine pair via shuffle. Partner is tid^1 (same warp).
    const float omax = __shfl_xor_sync(0xFFFFFFFFu, cmax, 1);
    const int   oidx = __shfl_xor_sync(0xFFFFFFFFu, cidx, 1);
    // First-occurrence tie-break: lower class index wins on equality.
    if (omax > cmax || (omax == cmax && oidx < cidx)) { cmax = omax; cidx = oidx; }

    float x, y, w, h, score, cls_f;
    if (half == 0) {
        const float inv = 1.0f / 1536.0f;
        const float bx = row[0] * inv;
        const float by = row[1] * inv;
        const float bw = row[2] * inv;
        const float bh = row[3] * inv;
        const float obj = row[4];
        x = bx - bw * 0.5f;
        y = by - bh * 0.5f;
        w = bx + bw * 0.5f;
        h = by + bh * 0.5f;
        score = obj * cmax;
        cls_f = (float)cidx;

        // Direct coalesced-ish outputs (even lanes; 2 sectors/instr, cheap):
        reinterpret_cast<float4*>(out)[a] = make_float4(x, y, w, h);
        out[(size_t)NUM_ANCHORS * 4 + a] = score;
        out[(size_t)NUM_ANCHORS * 5 + a] = cls_f;
    }

    // ---- Phase 3: stage detections in smem (reusing tile), write as float4 ----
    __syncthreads();   // all row reads from tile are done before overwrite
    if (half == 0) {
        float* __restrict__ det_s = tile + r * 6;   // 16 even lanes/warp -> distinct banks
        det_s[0] = x; det_s[1] = y; det_s[2] = w; det_s[3] = h;
        det_s[4] = cmax; det_s[5] = cls_f;
    }
    __syncthreads();

    // 128 rows * 6 floats = 768 floats = 192 float4, fully coalesced
    {
        float4* __restrict__ det_g = reinterpret_cast<float4*>(
            out + (size_t)NUM_ANCHORS * 6 + (size_t)base_row * 6);
        const float4* __restrict__ det_sv = reinterpret_cast<const float4*>(tile);
        if (tid < 192) {
            det_g[tid] = det_sv[tid];
        }
    }
}

extern "C" void kernel_launch(void* const* d_in, const int* in_sizes, int n_in,
                              void* d_out, int out_size)
{
    const float* pred = (const float*)d_in[0];
    // d_in[1] = score_threshold: unused by the reference outputs.
    float* out = (float*)d_out;

    const int blocks = NUM_ANCHORS / ROWS_PER_BLOCK;  // 1134
    yolo_decode_kernel<<<blocks, THREADS>>>(pred, out);
}

// round 4
// speedup vs baseline: 1.1866x; 1.1866x over previous
#include <cuda_runtime.h>
#include <cstdint>

// YoloV3Decoder: predictions (1, 145152, 85) fp32 -> tuple flattened as fp32:
//   [0 .. 4N)    bboxes (x,y,w,h)
//   [4N .. 5N)   scores
//   [5N .. 6N)   class_pred (as float)
//   [6N .. 12N)  detections (x,y,w,h,class_conf,class_pred)
// score_threshold input is unused by the reference outputs.

#define NUM_ANCHORS 145152
#define NUM_CH 85
#define ROWS_PER_BLOCK 128
#define THREADS 256
#define TILE_BYTES (ROWS_PER_BLOCK * NUM_CH * 4)  // 43520, multiple of 16

__global__ __launch_bounds__(THREADS) void yolo_decode_kernel(
    const float* __restrict__ pred, float* __restrict__ out)
{
    __shared__ float tile[ROWS_PER_BLOCK * NUM_CH];       // 43520 bytes
    __shared__ alignas(8) unsigned long long mbar;

    const int tid = threadIdx.x;
    const int base_row = blockIdx.x * ROWS_PER_BLOCK;

    const uint32_t tile_s = (uint32_t)__cvta_generic_to_shared(tile);
    const uint32_t mbar_s = (uint32_t)__cvta_generic_to_shared(&mbar);

    // ---- Phase 1: one bulk-async copy for the whole tile ----
    if (tid == 0) {
        asm volatile("mbarrier.init.shared.b64 [%0], %1;"
                     :: "r"(mbar_s), "r"(1) : "memory");
    }
    __syncthreads();
    if (tid == 0) {
        asm volatile("mbarrier.arrive.expect_tx.shared.b64 _, [%0], %1;"
                     :: "r"(mbar_s), "r"(TILE_BYTES) : "memory");
        const float* src = pred + (size_t)base_row * NUM_CH;  // 16B aligned (43520*blockIdx)
        asm volatile(
            "cp.async.bulk.shared::cta.global.mbarrier::complete_tx::bytes "
            "[%0], [%1], %2, [%3];"
            :: "r"(tile_s), "l"(src), "r"(TILE_BYTES), "r"(mbar_s) : "memory");
    }

    // All threads wait for the bulk copy (acquire: orders smem reads below).
    {
        uint32_t done;
        asm volatile(
            "{\n\t.reg .pred p;\n\t"
            "mbarrier.try_wait.parity.acquire.cta.shared::cta.b64 p, [%1], 0;\n\t"
            "selp.b32 %0, 1, 0, p;\n\t}"
            : "=r"(done) : "r"(mbar_s) : "memory");
        if (!done) {
            asm volatile(
                "{\n\t.reg .pred P1;\n\t"
                "WAIT_LOOP_%=:\n\t"
                "mbarrier.try_wait.parity.acquire.cta.shared::cta.b64 P1, [%0], 0, 0x989680;\n\t"
                "@P1 bra.uni WAIT_DONE_%=;\n\t"
                "bra.uni WAIT_LOOP_%=;\n\t"
                "WAIT_DONE_%=:\n\t}"
                :: "r"(mbar_s) : "memory");
        }
    }

    // ---- Phase 2: two threads per row; each scans 40 classes ----
    const int r    = tid >> 1;       // local row 0..127
    const int half = tid & 1;        // which 40-class chunk
    const int a    = base_row + r;   // global anchor
    const float* __restrict__ row = tile + r * NUM_CH;

    const int cbase = half * 40;
    float cmax = row[5 + cbase];
    int   cidx = cbase;
    #pragma unroll
    for (int c = 1; c < 40; ++c) {
        const float v = row[5 + cbase + c];
        if (v > cmax) { cmax = v; cidx = cbase + c; }
    }

    // Combine pair (partner tid^1, same warp); first-occurrence tie-break.
    const float omax = __shfl_xor_sync(0xFFFFFFFFu, cmax, 1);
    const int   oidx = __shfl_xor_sync(0xFFFFFFFFu, cidx, 1);
    if (omax > cmax || (omax == cmax && oidx < cidx)) { cmax = omax; cidx = oidx; }

    float x, y, w, h, score, cls_f;
    if (half == 0) {
        const float inv = 1.0f / 1536.0f;
        const float bx = row[0] * inv;
        const float by = row[1] * inv;
        const float bw = row[2] * inv;
        const float bh = row[3] * inv;
        const float obj = row[4];
        x = bx - bw * 0.5f;
        y = by - bh * 0.5f;
        w = bx + bw * 0.5f;
        h = by + bh * 0.5f;
        score = obj * cmax;
        cls_f = (float)cidx;

        reinterpret_cast<float4*>(out)[a] = make_float4(x, y, w, h);
        out[(size_t)NUM_ANCHORS * 4 + a] = score;
        out[(size_t)NUM_ANCHORS * 5 + a] = cls_f;
    }

    // ---- Phase 3: stage detections in smem (reuse tile), write as float4 ----
    __syncthreads();   // all tile reads done before overwrite
    if (half == 0) {
        float* __restrict__ det_s = tile + r * 6;
        det_s[0] = x; det_s[1] = y; det_s[2] = w; det_s[3] = h;
        det_s[4] = cmax; det_s[5] = cls_f;
    }
    __syncthreads();

    // 128 rows * 6 floats = 192 float4, fully coalesced
    {
        float4* __restrict__ det_g = reinterpret_cast<float4*>(
            out + (size_t)NUM_ANCHORS * 6 + (size_t)base_row * 6);
        const float4* __restrict__ det_sv = reinterpret_cast<const float4*>(tile);
        if (tid < 192) {
            det_g[tid] = det_sv[tid];
        }
    }
}

extern "C" void kernel_launch(void* const* d_in, const int* in_sizes, int n_in,
                              void* d_out, int out_size)
{
    const float* pred = (const float*)d_in[0];
    // d_in[1] = score_threshold: unused by the reference outputs.
    float* out = (float*)d_out;

    const int blocks = NUM_ANCHORS / ROWS_PER_BLOCK;  // 1134
    yolo_decode_kernel<<<blocks, THREADS>>>(pred, out);
}